// round 5
// baseline (speedup 1.0000x reference)
#include <cuda_runtime.h>
#include <cstdint>

#define DEVINL __device__ __forceinline__

namespace {

constexpr int HDIM = 128;
constexpr long long BROWS = 131072;
constexpr long long BH = BROWS * (long long)HDIM;
constexpr int THREADS = 512;
constexpr int M_TILE = 128;
constexpr int GRID = (int)(BROWS / M_TILE);  // 1024

constexpr int B_PITCH = 264;  // words; 264 % 32 == 8 -> conflict-free B frags

// smem word offsets
constexpr int SW_BIAS = 0;                      // 512 words
constexpr int SW_A = 512;                       // packed frags: 8bm*32s*32lane*4q = 32768 words
constexpr int SW_B0 = SW_A + 32768;             // 33280
constexpr int SW_B1 = SW_B0 + 32 * B_PITCH;
constexpr int SMEM_WORDS = SW_B1 + 32 * B_PITCH;
constexpr int SMEM_BYTES = SMEM_WORDS * 4;      // 200704 B

DEVINL void cp16(uint32_t saddr, const void* gaddr) {
    asm volatile("cp.async.cg.shared.global [%0], [%1], 16;"
                 :: "r"(saddr), "l"(gaddr) : "memory");
}
DEVINL void cp_commit() { asm volatile("cp.async.commit_group;" ::: "memory"); }
DEVINL void cp_wait0() { asm volatile("cp.async.wait_group 0;" ::: "memory"); }

DEVINL float totf32(float x) {
    uint32_t r;
    asm("cvt.rna.tf32.f32 %0, %1;" : "=r"(r) : "f"(x));
    return __uint_as_float(r);
}

DEVINL void mma8(float* d, const uint4& a, uint32_t b0, uint32_t b1) {
    asm volatile(
        "mma.sync.aligned.m16n8k8.row.col.f32.tf32.tf32.f32 "
        "{%0,%1,%2,%3}, {%4,%5,%6,%7}, {%8,%9}, {%0,%1,%2,%3};"
        : "+f"(d[0]), "+f"(d[1]), "+f"(d[2]), "+f"(d[3])
        : "r"(a.x), "r"(a.y), "r"(a.z), "r"(a.w), "r"(b0), "r"(b1));
}

DEVINL float sigf(float x) {
    return __fdividef(1.0f, 1.0f + __expf(-x));
}
DEVINL float tanhfast(float x) {
    return __fdividef(2.0f, 1.0f + __expf(-2.0f * x)) - 1.0f;
}

// Packed A-fragment word offset for element (r, k):
// consumer reads uint4 at index ((bm*32 + ks)*32 + lane), bm = r>>4, ks = k>>3.
DEVINL int pack_off(int r, int k) {
    int bm = r >> 4, rb = r & 15, s = k >> 3, kr = k & 7;
    int lane = ((rb & 7) << 2) | (kr & 3);
    int q = ((kr >> 2) << 1) | (rb >> 3);
    return ((bm * 32 + s) * 32 + lane) * 4 + q;
}

// Prefetch one 32k x 256col weight chunk into B buffer via 16B cp.async.
// kc in 0..7: kc<4 -> Wx rows kc*32..; kc>=4 -> Wh rows (kc-4)*32..
DEVINL void prefetch_chunk(const float* const* w8, int kc, int half,
                           uint32_t smem_base_u32, int buf, int tid) {
    const int n0 = half * 64;
    const uint32_t bbase = smem_base_u32 + (uint32_t)((buf ? SW_B1 : SW_B0) * 4);
#pragma unroll
    for (int i = 0; i < 4; i++) {
        int p = tid + i * THREADS;  // f4 index 0..2047
        int ii = p & 15;            // 16B unit within 64-col segment
        int g = (p >> 4) & 3;       // gate
        int r = p >> 6;             // k-row within chunk, 0..31
        const float* src = w8[(kc < 4 ? 0 : 4) + g] +
                           (size_t)((kc & 3) * 32 + r) * HDIM + n0 + ii * 4;
        uint32_t dst = bbase + (uint32_t)((r * B_PITCH + g * 64 + ii * 4) * 4);
        cp16(dst, src);
    }
}

__global__ void __launch_bounds__(THREADS, 1)
lstm_kernel(const float* __restrict__ x, const float* __restrict__ hprev,
            const float* __restrict__ cprev,
            const float* __restrict__ wxi, const float* __restrict__ wxf,
            const float* __restrict__ wxg, const float* __restrict__ wxo,
            const float* __restrict__ whi, const float* __restrict__ whf,
            const float* __restrict__ whg, const float* __restrict__ who,
            const float* __restrict__ bi, const float* __restrict__ bf,
            const float* __restrict__ bg, const float* __restrict__ bo,
            float* __restrict__ outh, float* __restrict__ outc, int writeC) {
    extern __shared__ float sm[];
    const int tid = threadIdx.x;
    const int lane = tid & 31;
    const int warp = tid >> 5;
    const int wM = warp >> 2;  // 0..3
    const int wN = warp & 3;   // 0..3
    const long long row0 = (long long)blockIdx.x * M_TILE;

    // biases -> smem [i|f|g|o] each 128 (512 threads: one element each)
    {
        int g = tid >> 7, e = tid & 127;
        const float* bsrc = (g == 0) ? bi : (g == 1) ? bf : (g == 2) ? bg : bo;
        sm[SW_BIAS + g * 128 + e] = bsrc[e];
    }

    // Stage A = [x | h] (128 rows x 256 k), tf32-rounded, fragment-packed.
#pragma unroll
    for (int i = 0; i < 8; i++) {
        int p = tid + i * THREADS;  // unit index 0..4095
        int r = p >> 5;
        int c4 = p & 31;
        float4 v = *reinterpret_cast<const float4*>(x + (row0 + r) * HDIM + c4 * 4);
        int o0 = pack_off(r, c4 * 4);
        sm[SW_A + o0]      = totf32(v.x);
        sm[SW_A + o0 + 4]  = totf32(v.y);
        sm[SW_A + o0 + 8]  = totf32(v.z);
        sm[SW_A + o0 + 12] = totf32(v.w);
        float4 w = *reinterpret_cast<const float4*>(hprev + (row0 + r) * HDIM + c4 * 4);
        int o1 = pack_off(r, c4 * 4 + 128);
        sm[SW_A + o1]      = totf32(w.x);
        sm[SW_A + o1 + 4]  = totf32(w.y);
        sm[SW_A + o1 + 8]  = totf32(w.z);
        sm[SW_A + o1 + 12] = totf32(w.w);
    }

    const uint32_t smem_u32 = (uint32_t)__cvta_generic_to_shared(sm);
    const float* w8[8] = {wxi, wxf, wxg, wxo, whi, whf, whg, who};

    prefetch_chunk(w8, 0, 0, smem_u32, 0, tid);
    cp_commit();

    float acc[2][8][4];
    const uint4* apack = reinterpret_cast<const uint4*>(sm + SW_A);

#pragma unroll 1
    for (int half = 0; half < 2; half++) {
#pragma unroll
        for (int mi = 0; mi < 2; mi++)
#pragma unroll
            for (int f = 0; f < 8; f++)
#pragma unroll
                for (int q = 0; q < 4; q++) acc[mi][f][q] = 0.0f;

#pragma unroll 1
        for (int kc = 0; kc < 8; kc++) {
            cp_wait0();
            __syncthreads();
            if (kc < 7) {
                prefetch_chunk(w8, kc + 1, half, smem_u32, (kc + 1) & 1, tid);
            } else if (half == 0) {
                prefetch_chunk(w8, 0, 1, smem_u32, 0, tid);
            }
            cp_commit();

            const float* Bb = sm + (kc & 1 ? SW_B1 : SW_B0);
#pragma unroll
            for (int s = 0; s < 4; s++) {
                const int ks = kc * 4 + s;  // global k-step 0..31
                uint4 afr[2];
#pragma unroll
                for (int mi = 0; mi < 2; mi++) {
                    afr[mi] = apack[((wM * 2 + mi) * 32 + ks) * 32 + lane];
                }
#pragma unroll
                for (int f = 0; f < 8; f++) {
                    const int cb = (f >> 1) * 64 + wN * 16 + (f & 1) * 8 + (lane >> 2);
                    const float* bp = Bb + (s * 8 + (lane & 3)) * B_PITCH + cb;
                    uint32_t b0 = __float_as_uint(bp[0]);
                    uint32_t b1 = __float_as_uint(bp[4 * B_PITCH]);
#pragma unroll
                    for (int mi = 0; mi < 2; mi++) mma8(acc[mi][f], afr[mi], b0, b1);
                }
            }
        }

        // Epilogue: cols n = half*64 + wN*16 + j*8 + 2*(lane&3) + {0,1}
        const float* bsm = sm + SW_BIAS;
#pragma unroll
        for (int mi = 0; mi < 2; mi++) {
#pragma unroll
            for (int rh = 0; rh < 2; rh++) {
                const long long m = row0 + wM * 32 + mi * 16 + (lane >> 2) + rh * 8;
#pragma unroll
                for (int j = 0; j < 2; j++) {
                    const int n = half * 64 + wN * 16 + j * 8 + 2 * (lane & 3);
                    float2 cp2 = *reinterpret_cast<const float2*>(cprev + m * HDIM + n);
                    float hv[2], cv[2];
#pragma unroll
                    for (int col = 0; col < 2; col++) {
                        float ai = acc[mi][0 + j][rh * 2 + col] + bsm[n + col];
                        float af = acc[mi][2 + j][rh * 2 + col] + bsm[128 + n + col];
                        float ag = acc[mi][4 + j][rh * 2 + col] + bsm[256 + n + col];
                        float ao = acc[mi][6 + j][rh * 2 + col] + bsm[384 + n + col];
                        float ig = sigf(ai);
                        float fg = sigf(af);
                        float og = sigf(ao);
                        float gg = tanhfast(ag);
                        float cpv = (col == 0) ? cp2.x : cp2.y;
                        float ct = fg * cpv + ig * gg;
                        cv[col] = ct;
                        hv[col] = og * tanhfast(ct);
                    }
                    *reinterpret_cast<float2*>(outh + m * HDIM + n) =
                        make_float2(hv[0], hv[1]);
                    if (writeC) {
                        *reinterpret_cast<float2*>(outc + m * HDIM + n) =
                            make_float2(cv[0], cv[1]);
                    }
                }
            }
        }
    }
}

}  // namespace

extern "C" void kernel_launch(void* const* d_in, const int* in_sizes, int n_in,
                              void* d_out, int out_size) {
    (void)in_sizes; (void)n_in;
    cudaFuncSetAttribute(lstm_kernel, cudaFuncAttributeMaxDynamicSharedMemorySize,
                         SMEM_BYTES);
    const float* x     = (const float*)d_in[0];
    const float* hprev = (const float*)d_in[1];
    const float* cprev = (const float*)d_in[2];
    const float* wxi   = (const float*)d_in[3];
    const float* wxf   = (const float*)d_in[4];
    const float* wxg   = (const float*)d_in[5];
    const float* wxo   = (const float*)d_in[6];
    const float* whi   = (const float*)d_in[7];
    const float* whf   = (const float*)d_in[8];
    const float* whg   = (const float*)d_in[9];
    const float* who   = (const float*)d_in[10];
    const float* bi    = (const float*)d_in[11];
    const float* bf    = (const float*)d_in[12];
    const float* bg    = (const float*)d_in[13];
    const float* bo    = (const float*)d_in[14];

    float* outh = (float*)d_out;
    const long long need2 = 2LL * BH;
    int writeC = ((long long)out_size >= need2) ? 1 : 0;
    float* outc = outh + BH;

    lstm_kernel<<<GRID, THREADS, SMEM_BYTES>>>(
        x, hprev, cprev, wxi, wxf, wxg, wxo, whi, whf, whg, who,
        bi, bf, bg, bo, outh, outc, writeC);
}

// round 8
// speedup vs baseline: 1.2028x; 1.2028x over previous
#include <cuda_runtime.h>
#include <cstdint>

#define DEVINL __device__ __forceinline__

namespace {

constexpr int HDIM = 128;
constexpr long long BROWS = 131072;
constexpr long long BH = BROWS * (long long)HDIM;
constexpr int THREADS = 256;
constexpr int M_TILE = 64;
constexpr int GRID = (int)(BROWS / M_TILE);  // 2048

constexpr int B_PITCH = 264;   // words; conflict-free B frag reads
constexpr int CHUNK_K = 16;    // k-rows per prefetch chunk

// smem word offsets
constexpr int SW_BIAS = 0;                        // 512 words
constexpr int SW_A = 512;                         // packed frags, 33-uint4 row stride
constexpr int A_WORDS = 4 * 32 * 33 * 4;          // 16896
constexpr int SW_B0 = SW_A + A_WORDS;             // 17408
constexpr int B_WORDS = CHUNK_K * B_PITCH;        // 4224
constexpr int SW_B1 = SW_B0 + B_WORDS;
constexpr int SMEM_WORDS = SW_B1 + B_WORDS;       // 25856
constexpr int SMEM_BYTES = SMEM_WORDS * 4;        // 103424 B -> 2 CTAs/SM

DEVINL void cp16(uint32_t saddr, const void* gaddr) {
    asm volatile("cp.async.cg.shared.global [%0], [%1], 16;"
                 :: "r"(saddr), "l"(gaddr) : "memory");
}
DEVINL void cp_commit() { asm volatile("cp.async.commit_group;" ::: "memory"); }
DEVINL void cp_wait0() { asm volatile("cp.async.wait_group 0;" ::: "memory"); }

DEVINL float totf32(float x) {
    uint32_t r;
    asm("cvt.rna.tf32.f32 %0, %1;" : "=r"(r) : "f"(x));
    return __uint_as_float(r);
}

DEVINL void mma8(float* d, const uint4& a, uint32_t b0, uint32_t b1) {
    asm volatile(
        "mma.sync.aligned.m16n8k8.row.col.f32.tf32.tf32.f32 "
        "{%0,%1,%2,%3}, {%4,%5,%6,%7}, {%8,%9}, {%0,%1,%2,%3};"
        : "+f"(d[0]), "+f"(d[1]), "+f"(d[2]), "+f"(d[3])
        : "r"(a.x), "r"(a.y), "r"(a.z), "r"(a.w), "r"(b0), "r"(b1));
}

DEVINL float sigf(float x) {
    return __fdividef(1.0f, 1.0f + __expf(-x));
}
DEVINL float tanhfast(float x) {
    return __fdividef(2.0f, 1.0f + __expf(-2.0f * x)) - 1.0f;
}

// Packed A-fragment word offset for element (r, k), r in 0..63, k in 0..255.
// Fragment row (bm, s) occupies 33 uint4s (32 data + 1 pad): strictly monotone,
// no cross-block overlap. Consumer reads uint4 at index ((bm*32 + ks)*33 + lane).
DEVINL int pack_off(int r, int k) {
    int bm = r >> 4, rb = r & 15, s = k >> 3, kr = k & 7;
    int lane_f = ((rb & 7) << 2) | (kr & 3);
    int q = ((kr >> 2) << 1) | (rb >> 3);
    return ((bm * 32 + s) * 33 + lane_f) * 4 + q;
}

// Prefetch one CHUNK_K x 256col weight chunk (4 gates x 64 h-cols of `half`).
// kc 0..15: kc<8 -> Wx rows kc*16.. ; kc>=8 -> Wh rows (kc-8)*16..
DEVINL void prefetch_chunk(const float* const* w8, int kc, int half,
                           uint32_t smem_base_u32, int buf, int tid) {
    const int n0 = half * 64;
    const uint32_t bbase = smem_base_u32 + (uint32_t)((buf ? SW_B1 : SW_B0) * 4);
#pragma unroll
    for (int i = 0; i < 4; i++) {
        int p = tid + i * THREADS;  // 0..1023
        int ii = p & 15;            // 16B unit within 64-col segment
        int g = (p >> 4) & 3;       // gate
        int r = p >> 6;             // k-row within chunk, 0..15
        const float* src = w8[(kc < 8 ? 0 : 4) + g] +
                           (size_t)((kc & 7) * CHUNK_K + r) * HDIM + n0 + ii * 4;
        uint32_t dst = bbase + (uint32_t)((r * B_PITCH + g * 64 + ii * 4) * 4);
        cp16(dst, src);
    }
}

__global__ void __launch_bounds__(THREADS, 2)
lstm_kernel(const float* __restrict__ x, const float* __restrict__ hprev,
            const float* __restrict__ cprev,
            const float* __restrict__ wxi, const float* __restrict__ wxf,
            const float* __restrict__ wxg, const float* __restrict__ wxo,
            const float* __restrict__ whi, const float* __restrict__ whf,
            const float* __restrict__ whg, const float* __restrict__ who,
            const float* __restrict__ bi, const float* __restrict__ bf,
            const float* __restrict__ bg, const float* __restrict__ bo,
            float* __restrict__ outh, float* __restrict__ outc, int writeC) {
    extern __shared__ float sm[];
    const int tid = threadIdx.x;
    const int lane = tid & 31;
    const int wN = tid >> 5;  // 0..7
    const long long row0 = (long long)blockIdx.x * M_TILE;

    // biases -> smem [i|f|g|o] each 128
    sm[SW_BIAS + tid] = (tid < 128) ? bi[tid] : bf[tid - 128];
    sm[SW_BIAS + 256 + tid] = (tid < 128) ? bg[tid] : bo[tid - 128];

    // Stage A = [x | h] (64 rows x 256 k), tf32-rounded, fragment-packed.
#pragma unroll
    for (int i = 0; i < 8; i++) {
        int p = tid + i * THREADS;  // unit 0..2047
        int r = p >> 5;
        int c4 = p & 31;
        float4 v = *reinterpret_cast<const float4*>(x + (row0 + r) * HDIM + c4 * 4);
        int o0 = pack_off(r, c4 * 4);
        sm[SW_A + o0]      = totf32(v.x);
        sm[SW_A + o0 + 4]  = totf32(v.y);
        sm[SW_A + o0 + 8]  = totf32(v.z);
        sm[SW_A + o0 + 12] = totf32(v.w);
        float4 w = *reinterpret_cast<const float4*>(hprev + (row0 + r) * HDIM + c4 * 4);
        int o1 = pack_off(r, c4 * 4 + 128);
        sm[SW_A + o1]      = totf32(w.x);
        sm[SW_A + o1 + 4]  = totf32(w.y);
        sm[SW_A + o1 + 8]  = totf32(w.z);
        sm[SW_A + o1 + 12] = totf32(w.w);
    }

    const uint32_t smem_u32 = (uint32_t)__cvta_generic_to_shared(sm);
    const float* w8[8] = {wxi, wxf, wxg, wxo, whi, whf, whg, who};

    prefetch_chunk(w8, 0, 0, smem_u32, 0, tid);
    cp_commit();

    float acc[4][4][4];
    const uint4* apack = reinterpret_cast<const uint4*>(sm + SW_A);

#pragma unroll 1
    for (int half = 0; half < 2; half++) {
#pragma unroll
        for (int mi = 0; mi < 4; mi++)
#pragma unroll
            for (int f = 0; f < 4; f++)
#pragma unroll
                for (int q = 0; q < 4; q++) acc[mi][f][q] = 0.0f;

#pragma unroll 1
        for (int kc = 0; kc < 16; kc++) {
            cp_wait0();
            __syncthreads();
            if (kc < 15) {
                prefetch_chunk(w8, kc + 1, half, smem_u32, (kc + 1) & 1, tid);
                cp_commit();
            } else if (half == 0) {
                prefetch_chunk(w8, 0, 1, smem_u32, 0, tid);
                cp_commit();
            }

            const float* Bb = sm + (kc & 1 ? SW_B1 : SW_B0);
#pragma unroll
            for (int s2 = 0; s2 < 2; s2++) {
                const int ks = kc * 2 + s2;  // global k-step 0..31
                uint4 afr[4];
#pragma unroll
                for (int mi = 0; mi < 4; mi++) {
                    afr[mi] = apack[(mi * 32 + ks) * 33 + lane];
                }
#pragma unroll
                for (int f = 0; f < 4; f++) {
                    const int cb = f * 64 + wN * 8 + (lane >> 2);
                    const float* bp = Bb + (s2 * 8 + (lane & 3)) * B_PITCH + cb;
                    uint32_t b0 = __float_as_uint(bp[0]);
                    uint32_t b1 = __float_as_uint(bp[4 * B_PITCH]);
#pragma unroll
                    for (int mi = 0; mi < 4; mi++) mma8(acc[mi][f], afr[mi], b0, b1);
                }
            }
        }

        // Epilogue: cols n = half*64 + wN*8 + 2*(lane&3) + {0,1}
        const float* bsm = sm + SW_BIAS;
        const int n = half * 64 + wN * 8 + 2 * (lane & 3);
#pragma unroll
        for (int mi = 0; mi < 4; mi++) {
#pragma unroll
            for (int rh = 0; rh < 2; rh++) {
                const long long m = row0 + mi * 16 + (lane >> 2) + rh * 8;
                float2 cp2 = *reinterpret_cast<const float2*>(cprev + m * HDIM + n);
                float hv[2], cv[2];
#pragma unroll
                for (int col = 0; col < 2; col++) {
                    float ai = acc[mi][0][rh * 2 + col] + bsm[n + col];
                    float af = acc[mi][1][rh * 2 + col] + bsm[128 + n + col];
                    float ag = acc[mi][2][rh * 2 + col] + bsm[256 + n + col];
                    float ao = acc[mi][3][rh * 2 + col] + bsm[384 + n + col];
                    float ig = sigf(ai);
                    float fg = sigf(af);
                    float og = sigf(ao);
                    float gg = tanhfast(ag);
                    float cpv = (col == 0) ? cp2.x : cp2.y;
                    float ct = fg * cpv + ig * gg;
                    cv[col] = ct;
                    hv[col] = og * tanhfast(ct);
                }
                *reinterpret_cast<float2*>(outh + m * HDIM + n) =
                    make_float2(hv[0], hv[1]);
                if (writeC) {
                    *reinterpret_cast<float2*>(outc + m * HDIM + n) =
                        make_float2(cv[0], cv[1]);
                }
            }
        }
    }
}

}  // namespace

extern "C" void kernel_launch(void* const* d_in, const int* in_sizes, int n_in,
                              void* d_out, int out_size) {
    (void)in_sizes; (void)n_in;
    cudaFuncSetAttribute(lstm_kernel, cudaFuncAttributeMaxDynamicSharedMemorySize,
                         SMEM_BYTES);
    const float* x     = (const float*)d_in[0];
    const float* hprev = (const float*)d_in[1];
    const float* cprev = (const float*)d_in[2];
    const float* wxi   = (const float*)d_in[3];
    const float* wxf   = (const float*)d_in[4];
    const float* wxg   = (const float*)d_in[5];
    const float* wxo   = (const float*)d_in[6];
    const float* whi   = (const float*)d_in[7];
    const float* whf   = (const float*)d_in[8];
    const float* whg   = (const float*)d_in[9];
    const float* who   = (const float*)d_in[10];
    const float* bi    = (const float*)d_in[11];
    const float* bf    = (const float*)d_in[12];
    const float* bg    = (const float*)d_in[13];
    const float* bo    = (const float*)d_in[14];

    float* outh = (float*)d_out;
    const long long need2 = 2LL * BH;
    int writeC = ((long long)out_size >= need2) ? 1 : 0;
    float* outc = outh + BH;

    lstm_kernel<<<GRID, THREADS, SMEM_BYTES>>>(
        x, hprev, cprev, wxi, wxf, wxg, wxo, whi, whf, whg, who,
        bi, bf, bg, bo, outh, outc, writeC);
}

// round 9
// speedup vs baseline: 1.3317x; 1.1071x over previous
#include <cuda_runtime.h>
#include <cuda_fp16.h>
#include <cstdint>

#define DEVINL __device__ __forceinline__

namespace {

constexpr int HDIM = 128;
constexpr long long BROWS = 131072;
constexpr long long BH = BROWS * (long long)HDIM;
constexpr int THREADS = 256;
constexpr int M_TILE = 64;
constexpr int GRID = (int)(BROWS / M_TILE);  // 2048

constexpr int B_PITCH = 264;     // fp16x2 words per kpair-row (256 data + 8 pad)
constexpr int CHUNKS = 16;       // 16 chunks of 32 k-rows (8 per n-half)
constexpr int CHUNK_WORDS = 16 * 256;  // dense: 16 kpair-rows x 256 cols

// smem word (uint32) offsets
constexpr int SW_BIAS = 0;                        // 512 words (fp32 biases)
constexpr int SW_A = 512;                         // packed A frags: 4bm*16ks*33 uint4
constexpr int A_WORDS = 4 * 16 * 33 * 4;          // 8448
constexpr int SW_B0 = SW_A + A_WORDS;             // 8960
constexpr int B_BUF_WORDS = 16 * B_PITCH;         // 4224
constexpr int SMEM_WORDS = SW_B0 + 3 * B_BUF_WORDS;  // 21632
constexpr int SMEM_BYTES = SMEM_WORDS * 4;        // 86528 B -> 2 CTAs/SM

// Preconverted weights: 16 chunks x 4096 fp16x2 words = 256 KB
__device__ uint32_t g_wpack[CHUNKS * CHUNK_WORDS];

DEVINL void cp16(uint32_t saddr, const void* gaddr) {
    asm volatile("cp.async.cg.shared.global [%0], [%1], 16;"
                 :: "r"(saddr), "l"(gaddr) : "memory");
}
DEVINL void cp_commit() { asm volatile("cp.async.commit_group;" ::: "memory"); }
DEVINL void cp_wait0() { asm volatile("cp.async.wait_group 0;" ::: "memory"); }
DEVINL void cp_wait1() { asm volatile("cp.async.wait_group 1;" ::: "memory"); }

DEVINL uint32_t packh2(float lo, float hi) {
    __half2 h = __floats2half2_rn(lo, hi);
    return *reinterpret_cast<uint32_t*>(&h);
}

DEVINL void mma16(float* d, const uint4& a, uint32_t b0, uint32_t b1) {
    asm volatile(
        "mma.sync.aligned.m16n8k16.row.col.f32.f16.f16.f32 "
        "{%0,%1,%2,%3}, {%4,%5,%6,%7}, {%8,%9}, {%0,%1,%2,%3};"
        : "+f"(d[0]), "+f"(d[1]), "+f"(d[2]), "+f"(d[3])
        : "r"(a.x), "r"(a.y), "r"(a.z), "r"(a.w), "r"(b0), "r"(b1));
}

DEVINL float sigf(float x) {
    return __fdividef(1.0f, 1.0f + __expf(-x));
}
DEVINL float tanhfast(float x) {
    return __fdividef(2.0f, 1.0f + __expf(-2.0f * x)) - 1.0f;
}

// Packed A word index for the fp16x2 word holding (r, k),(r, k+1), k even.
// m16n8k16 A fragment: lane l, regs q0..q3. Consumer reads uint4 at
// index ((bm*16 + ks)*33 + lane).
DEVINL int widx(int r, int k) {
    int bm = r >> 4, rb = r & 15, ks = k >> 4, kr = k & 15;
    int lane_f = ((rb & 7) << 2) | ((kr & 7) >> 1);
    int q = ((kr >> 3) << 1) | (rb >> 3);
    return (((bm * 16 + ks) * 33 + lane_f) << 2) + q;
}

// ---------------- pre-pack kernel: weights fp32 -> fp16x2 chunk image -------
__global__ void pack_weights(const float* __restrict__ wxi, const float* __restrict__ wxf,
                             const float* __restrict__ wxg, const float* __restrict__ wxo,
                             const float* __restrict__ whi, const float* __restrict__ whf,
                             const float* __restrict__ whg, const float* __restrict__ who) {
    const float* w8[8] = {wxi, wxf, wxg, wxo, whi, whf, whg, who};
    int idx = blockIdx.x * blockDim.x + threadIdx.x;  // 0..65535
    int c = idx >> 12;        // chunk 0..15
    int j = idx & 4095;       // word within chunk
    int r = j >> 8;           // kpair row 0..15
    int col = j & 255;        // gate*64 + noff
    int g = col >> 6;
    int half = c >> 3, sub = c & 7;
    int n = half * 64 + (col & 63);
    int k = (sub & 3) * 32 + r * 2;
    const float* w = w8[(sub < 4 ? 0 : 4) + g];
    float lo = w[(size_t)k * HDIM + n];
    float hi = w[(size_t)(k + 1) * HDIM + n];
    g_wpack[idx] = packh2(lo, hi);
}

// Prefetch chunk c into B buffer buf (pure cp.async copy with pitch remap).
DEVINL void prefetch_chunk(int c, uint32_t smem_base_u32, int buf, int tid) {
    const uint32_t bbase = smem_base_u32 + (uint32_t)((SW_B0 + buf * B_BUF_WORDS) * 4);
    const uint32_t* src_base = g_wpack + c * CHUNK_WORDS;
#pragma unroll
    for (int i = 0; i < 4; i++) {
        int p = tid + i * THREADS;  // 16B line 0..1023
        int r = p >> 6, c16 = p & 63;
        const void* src = src_base + r * 256 + c16 * 4;
        uint32_t dst = bbase + (uint32_t)((r * B_PITCH + c16 * 4) * 4);
        cp16(dst, src);
    }
}

__global__ void __launch_bounds__(THREADS, 2)
lstm_kernel(const float* __restrict__ x, const float* __restrict__ hprev,
            const float* __restrict__ cprev,
            const float* __restrict__ bi, const float* __restrict__ bf,
            const float* __restrict__ bg, const float* __restrict__ bo,
            float* __restrict__ outh, float* __restrict__ outc, int writeC) {
    extern __shared__ float sm[];
    uint32_t* smw = reinterpret_cast<uint32_t*>(sm);
    const int tid = threadIdx.x;
    const int lane = tid & 31;
    const int wN = tid >> 5;  // 0..7
    const long long row0 = (long long)blockIdx.x * M_TILE;

    // biases -> smem [i|f|g|o] each 128 (fp32)
    sm[SW_BIAS + tid] = (tid < 128) ? bi[tid] : bf[tid - 128];
    sm[SW_BIAS + 256 + tid] = (tid < 128) ? bg[tid] : bo[tid - 128];

    // Stage A = [x | h] (64 rows x 256 k), fp16 fragment-packed.
#pragma unroll
    for (int i = 0; i < 8; i++) {
        int p = tid + i * THREADS;  // float4 unit 0..2047
        int r = p >> 5;
        int c4 = p & 31;
        float4 v = *reinterpret_cast<const float4*>(x + (row0 + r) * HDIM + c4 * 4);
        int o0 = widx(r, c4 * 4);
        smw[SW_A + o0]     = packh2(v.x, v.y);
        smw[SW_A + o0 + 4] = packh2(v.z, v.w);
        float4 w = *reinterpret_cast<const float4*>(hprev + (row0 + r) * HDIM + c4 * 4);
        int o1 = widx(r, c4 * 4 + 128);
        smw[SW_A + o1]     = packh2(w.x, w.y);
        smw[SW_A + o1 + 4] = packh2(w.z, w.w);
    }

    const uint32_t smem_u32 = (uint32_t)__cvta_generic_to_shared(sm);

    prefetch_chunk(0, smem_u32, 0, tid);
    cp_commit();
    prefetch_chunk(1, smem_u32, 1, tid);
    cp_commit();

    float acc[4][4][4];
#pragma unroll
    for (int mi = 0; mi < 4; mi++)
#pragma unroll
        for (int f = 0; f < 4; f++)
#pragma unroll
            for (int q = 0; q < 4; q++) acc[mi][f][q] = 0.0f;

    const uint4* apack = reinterpret_cast<const uint4*>(smw + SW_A);
    const float* bsm = sm + SW_BIAS;

#pragma unroll 1
    for (int c = 0; c < CHUNKS; c++) {
        if (c < CHUNKS - 2) cp_wait1(); else cp_wait0();
        __syncthreads();
        if (c + 2 < CHUNKS) {
            prefetch_chunk(c + 2, smem_u32, (c + 2) % 3, tid);
            cp_commit();
        }

        const uint32_t* Bb = smw + SW_B0 + (c % 3) * B_BUF_WORDS;
#pragma unroll
        for (int s = 0; s < 2; s++) {
            const int ks = (c & 7) * 2 + s;  // k16-step 0..15
            uint4 afr[4];
#pragma unroll
            for (int mi = 0; mi < 4; mi++) {
                afr[mi] = apack[(mi * 16 + ks) * 33 + lane];
            }
#pragma unroll
            for (int f = 0; f < 4; f++) {
                const int cb = f * 64 + wN * 8 + (lane >> 2);
                uint32_t b0 = Bb[(s * 8 + (lane & 3)) * B_PITCH + cb];
                uint32_t b1 = Bb[(s * 8 + (lane & 3) + 4) * B_PITCH + cb];
#pragma unroll
                for (int mi = 0; mi < 4; mi++) mma16(acc[mi][f], afr[mi], b0, b1);
            }
        }

        // Epilogue after each half's 8 chunks (c == 7 and c == 15).
        if ((c & 7) == 7) {
            const int half = c >> 3;
            const int n = half * 64 + wN * 8 + 2 * (lane & 3);
#pragma unroll
            for (int mi = 0; mi < 4; mi++) {
#pragma unroll
                for (int rh = 0; rh < 2; rh++) {
                    const long long m = row0 + mi * 16 + (lane >> 2) + rh * 8;
                    float2 cp2 = *reinterpret_cast<const float2*>(cprev + m * HDIM + n);
                    float hv[2], cv[2];
#pragma unroll
                    for (int col = 0; col < 2; col++) {
                        float ai = acc[mi][0][rh * 2 + col] + bsm[n + col];
                        float af = acc[mi][1][rh * 2 + col] + bsm[128 + n + col];
                        float ag = acc[mi][2][rh * 2 + col] + bsm[256 + n + col];
                        float ao = acc[mi][3][rh * 2 + col] + bsm[384 + n + col];
                        float ig = sigf(ai);
                        float fg = sigf(af);
                        float og = sigf(ao);
                        float gg = tanhfast(ag);
                        float cpv = (col == 0) ? cp2.x : cp2.y;
                        float ct = fg * cpv + ig * gg;
                        cv[col] = ct;
                        hv[col] = og * tanhfast(ct);
                    }
                    *reinterpret_cast<float2*>(outh + m * HDIM + n) =
                        make_float2(hv[0], hv[1]);
                    if (writeC) {
                        *reinterpret_cast<float2*>(outc + m * HDIM + n) =
                            make_float2(cv[0], cv[1]);
                    }
                }
            }
            if (half == 0) {
#pragma unroll
                for (int mi = 0; mi < 4; mi++)
#pragma unroll
                    for (int f = 0; f < 4; f++)
#pragma unroll
                        for (int q = 0; q < 4; q++) acc[mi][f][q] = 0.0f;
            }
        }
    }
}

}  // namespace

extern "C" void kernel_launch(void* const* d_in, const int* in_sizes, int n_in,
                              void* d_out, int out_size) {
    (void)in_sizes; (void)n_in;
    cudaFuncSetAttribute(lstm_kernel, cudaFuncAttributeMaxDynamicSharedMemorySize,
                         SMEM_BYTES);
    const float* x     = (const float*)d_in[0];
    const float* hprev = (const float*)d_in[1];
    const float* cprev = (const float*)d_in[2];
    const float* wxi   = (const float*)d_in[3];
    const float* wxf   = (const float*)d_in[4];
    const float* wxg   = (const float*)d_in[5];
    const float* wxo   = (const float*)d_in[6];
    const float* whi   = (const float*)d_in[7];
    const float* whf   = (const float*)d_in[8];
    const float* whg   = (const float*)d_in[9];
    const float* who   = (const float*)d_in[10];
    const float* bi    = (const float*)d_in[11];
    const float* bf    = (const float*)d_in[12];
    const float* bg    = (const float*)d_in[13];
    const float* bo    = (const float*)d_in[14];

    float* outh = (float*)d_out;
    const long long need2 = 2LL * BH;
    int writeC = ((long long)out_size >= need2) ? 1 : 0;
    float* outc = outh + BH;

    pack_weights<<<256, 256>>>(wxi, wxf, wxg, wxo, whi, whf, whg, who);
    lstm_kernel<<<GRID, THREADS, SMEM_BYTES>>>(
        x, hprev, cprev, bi, bf, bg, bo, outh, outc, writeC);
}

// round 10
// speedup vs baseline: 1.8939x; 1.4222x over previous
#include <cuda_runtime.h>
#include <cuda_fp16.h>
#include <cstdint>

#define DEVINL __device__ __forceinline__

namespace {

constexpr int HDIM = 128;
constexpr long long BROWS = 131072;
constexpr long long BH = BROWS * (long long)HDIM;
constexpr int THREADS = 512;
constexpr int M_TILE = 128;
constexpr int GRID = (int)(BROWS / M_TILE) * 2;  // 2048 (m-tile x half)

// smem word (uint32) offsets
constexpr int SW_BIAS = 0;                        // 256 words (fp32, this half's 4x64)
constexpr int SW_A = 256;                         // packed A frags: 8bm*16ks*33 uint4
constexpr int A_WORDS = 8 * 16 * 33 * 4;          // 16896
constexpr int SW_B = SW_A + A_WORDS;              // 17152
constexpr int B_WORDS = 16 * 16 * 32 * 4;         // 32768 (16 ks * 16 fq * 32 lanes * uint4)
constexpr int SMEM_WORDS = SW_B + B_WORDS;        // 49920
constexpr int SMEM_BYTES = SMEM_WORDS * 4;        // 199680 B -> 1 CTA/SM

// Pre-packed weights, fragment order: word idx =
// ((half*16 + ks)*16 + fq)*128 + lane*4 + wq,  fq = gate*4 + wn
__device__ uint32_t g_wpack[2 * 16 * 16 * 128];

DEVINL void cp16(uint32_t saddr, const void* gaddr) {
    asm volatile("cp.async.cg.shared.global [%0], [%1], 16;"
                 :: "r"(saddr), "l"(gaddr) : "memory");
}
DEVINL void cp_commit() { asm volatile("cp.async.commit_group;" ::: "memory"); }

template <int P>
DEVINL void wait_and_sync() {
    asm volatile("cp.async.wait_group %0;" :: "n"(P) : "memory");
    __syncthreads();
}

DEVINL uint32_t packh2(float lo, float hi) {
    __half2 h = __floats2half2_rn(lo, hi);
    return *reinterpret_cast<uint32_t*>(&h);
}

DEVINL void mma16(float* d, const uint4& a, uint32_t b0, uint32_t b1) {
    asm volatile(
        "mma.sync.aligned.m16n8k16.row.col.f32.f16.f16.f32 "
        "{%0,%1,%2,%3}, {%4,%5,%6,%7}, {%8,%9}, {%0,%1,%2,%3};"
        : "+f"(d[0]), "+f"(d[1]), "+f"(d[2]), "+f"(d[3])
        : "r"(a.x), "r"(a.y), "r"(a.z), "r"(a.w), "r"(b0), "r"(b1));
}

DEVINL float sigf(float x) {
    return __fdividef(1.0f, 1.0f + __expf(-x));
}
DEVINL float tanhfast(float x) {
    return __fdividef(2.0f, 1.0f + __expf(-2.0f * x)) - 1.0f;
}

// Packed A word index for the fp16x2 word holding (r,k),(r,k+1), k even.
// Consumer reads uint4 at ((bm*16 + ks)*33 + lane), bm = r>>4 in 0..7.
DEVINL int widx(int r, int k) {
    int bm = r >> 4, rb = r & 15, ks = k >> 4, kr = k & 15;
    int lane_f = ((rb & 7) << 2) | ((kr & 7) >> 1);
    int q = ((kr >> 3) << 1) | (rb >> 3);
    return (((bm * 16 + ks) * 33 + lane_f) << 2) + q;
}

// ---- pre-pack: weights fp32 -> fp16x2 fragment-ordered image (256 KB) ----
__global__ void pack_weights(const float* __restrict__ wxi, const float* __restrict__ wxf,
                             const float* __restrict__ wxg, const float* __restrict__ wxo,
                             const float* __restrict__ whi, const float* __restrict__ whf,
                             const float* __restrict__ whg, const float* __restrict__ who) {
    const float* wx[4] = {wxi, wxf, wxg, wxo};
    const float* wh[4] = {whi, whf, whg, who};
    int idx = blockIdx.x * blockDim.x + threadIdx.x;  // 0..65535
    int half = idx >> 15;
    int r1 = idx & 32767;
    int ks = r1 >> 11;
    int r2 = r1 & 2047;
    int fq = r2 >> 7;
    int r3 = r2 & 127;
    int lane = r3 >> 2;
    int wq = r3 & 3;
    int g = fq >> 2, wn = fq & 3;
    int subn = wq >> 1, bsel = wq & 1;
    int n = half * 64 + wn * 16 + subn * 8 + (lane >> 2);
    int k0 = ks * 16 + 2 * (lane & 3) + bsel * 8;
    const float* w = (k0 < 128) ? wx[g] : wh[g];
    int kk = k0 & 127;
    float lo = w[(size_t)kk * HDIM + n];
    float hi = w[(size_t)(kk + 1) * HDIM + n];
    g_wpack[idx] = packh2(lo, hi);
}

struct Frag { float v[4]; };

__global__ void __launch_bounds__(THREADS, 1)
lstm_kernel(const float* __restrict__ x, const float* __restrict__ hprev,
            const float* __restrict__ cprev,
            const float* __restrict__ bi, const float* __restrict__ bf,
            const float* __restrict__ bg, const float* __restrict__ bo,
            float* __restrict__ outh, float* __restrict__ outc, int writeC) {
    extern __shared__ float sm[];
    uint32_t* smw = reinterpret_cast<uint32_t*>(sm);
    const int tid = threadIdx.x;
    const int lane = tid & 31;
    const int wid = tid >> 5;
    const int wM = wid >> 2;  // 0..3
    const int wN = wid & 3;   // 0..3
    const int mtile = blockIdx.x >> 1;
    const int half = blockIdx.x & 1;
    const long long row0 = (long long)mtile * M_TILE;
    const uint32_t smem_u32 = (uint32_t)__cvta_generic_to_shared(sm);

    // --- issue B prefetch first (8 groups of 2 k-steps = 16 KB each) ---
    const uint32_t* wsrc = g_wpack + half * 32768;
    const uint32_t bdst = smem_u32 + SW_B * 4;
#pragma unroll
    for (int p = 0; p < 8; p++) {
#pragma unroll
        for (int i = 0; i < 2; i++) {
            int l = tid + i * THREADS;           // line 0..1023 in group
            int word = p * 4096 + l * 4;
            cp16(bdst + word * 4, wsrc + word);
        }
        cp_commit();
    }

    // --- biases for this half: [i|f|g|o] x 64 cols ---
    if (tid < 256) {
        int g = tid >> 6, c = tid & 63;
        const float* bsrc = (g == 0) ? bi : (g == 1) ? bf : (g == 2) ? bg : bo;
        sm[SW_BIAS + tid] = bsrc[half * 64 + c];
    }

    // --- stage A = [x | h] (128 rows x 256 k), fp16 fragment-packed ---
#pragma unroll
    for (int i = 0; i < 8; i++) {
        int p = tid + i * THREADS;  // float4 unit 0..4095
        int r = p >> 5;
        int c4 = p & 31;
        float4 v = *reinterpret_cast<const float4*>(x + (row0 + r) * HDIM + c4 * 4);
        int o0 = widx(r, c4 * 4);
        smw[SW_A + o0]     = packh2(v.x, v.y);
        smw[SW_A + o0 + 4] = packh2(v.z, v.w);
        float4 w = *reinterpret_cast<const float4*>(hprev + (row0 + r) * HDIM + c4 * 4);
        int o1 = widx(r, c4 * 4 + 128);
        smw[SW_A + o1]     = packh2(w.x, w.y);
        smw[SW_A + o1 + 4] = packh2(w.z, w.w);
    }

    float acc[2][8][4];
#pragma unroll
    for (int mi = 0; mi < 2; mi++)
#pragma unroll
        for (int f = 0; f < 8; f++)
#pragma unroll
            for (int q = 0; q < 4; q++) acc[mi][f][q] = 0.0f;

    const uint4* apack = reinterpret_cast<const uint4*>(smw + SW_A);
    const uint4* bpack = reinterpret_cast<const uint4*>(smw + SW_B);

    // One k16-step: 2 A LDS.128 + 4 B LDS.128 + 16 HMMA, no barriers.
#define DO_KS(ks)                                                              \
    {                                                                          \
        uint4 afr[2];                                                          \
        afr[0] = apack[((wM * 2 + 0) * 16 + (ks)) * 33 + lane];                \
        afr[1] = apack[((wM * 2 + 1) * 16 + (ks)) * 33 + lane];                \
        uint4 bv0 = bpack[((ks) * 16 + 0 * 4 + wN) * 32 + lane];               \
        uint4 bv1 = bpack[((ks) * 16 + 1 * 4 + wN) * 32 + lane];               \
        uint4 bv2 = bpack[((ks) * 16 + 2 * 4 + wN) * 32 + lane];               \
        uint4 bv3 = bpack[((ks) * 16 + 3 * 4 + wN) * 32 + lane];               \
        for (int mi = 0; mi < 2; mi++) {                                       \
            mma16(acc[mi][0], afr[mi], bv0.x, bv0.y);                          \
            mma16(acc[mi][1], afr[mi], bv0.z, bv0.w);                          \
            mma16(acc[mi][2], afr[mi], bv1.x, bv1.y);                          \
            mma16(acc[mi][3], afr[mi], bv1.z, bv1.w);                          \
            mma16(acc[mi][4], afr[mi], bv2.x, bv2.y);                          \
            mma16(acc[mi][5], afr[mi], bv2.z, bv2.w);                          \
            mma16(acc[mi][6], afr[mi], bv3.x, bv3.y);                          \
            mma16(acc[mi][7], afr[mi], bv3.z, bv3.w);                          \
        }                                                                      \
    }

    wait_and_sync<7>(); DO_KS(0);  DO_KS(1);
    wait_and_sync<6>(); DO_KS(2);  DO_KS(3);
    wait_and_sync<5>(); DO_KS(4);  DO_KS(5);
    wait_and_sync<4>(); DO_KS(6);  DO_KS(7);
    wait_and_sync<3>(); DO_KS(8);  DO_KS(9);
    wait_and_sync<2>(); DO_KS(10); DO_KS(11);
    wait_and_sync<1>(); DO_KS(12); DO_KS(13);
    wait_and_sync<0>(); DO_KS(14); DO_KS(15);
#undef DO_KS

    // --- epilogue: warp owns h-cols [wN*16, wN*16+16) of this half, all gates ---
    const float* bsm = sm + SW_BIAS;
#pragma unroll
    for (int mi = 0; mi < 2; mi++) {
#pragma unroll
        for (int rh = 0; rh < 2; rh++) {
            const long long m = row0 + wM * 32 + mi * 16 + (lane >> 2) + rh * 8;
#pragma unroll
            for (int subn = 0; subn < 2; subn++) {
                const int nloc = wN * 16 + subn * 8 + 2 * (lane & 3);
                const int n = half * 64 + nloc;
                float2 cp2 = *reinterpret_cast<const float2*>(cprev + m * HDIM + n);
                float hv[2], cv[2];
#pragma unroll
                for (int col = 0; col < 2; col++) {
                    float ai = acc[mi][0 + subn][rh * 2 + col] + bsm[nloc + col];
                    float af = acc[mi][2 + subn][rh * 2 + col] + bsm[64 + nloc + col];
                    float ag = acc[mi][4 + subn][rh * 2 + col] + bsm[128 + nloc + col];
                    float ao = acc[mi][6 + subn][rh * 2 + col] + bsm[192 + nloc + col];
                    float ig = sigf(ai);
                    float fg = sigf(af);
                    float og = sigf(ao);
                    float gg = tanhfast(ag);
                    float cpv = (col == 0) ? cp2.x : cp2.y;
                    float ct = fg * cpv + ig * gg;
                    cv[col] = ct;
                    hv[col] = og * tanhfast(ct);
                }
                *reinterpret_cast<float2*>(outh + m * HDIM + n) =
                    make_float2(hv[0], hv[1]);
                if (writeC) {
                    *reinterpret_cast<float2*>(outc + m * HDIM + n) =
                        make_float2(cv[0], cv[1]);
                }
            }
        }
    }
}

}  // namespace

extern "C" void kernel_launch(void* const* d_in, const int* in_sizes, int n_in,
                              void* d_out, int out_size) {
    (void)in_sizes; (void)n_in;
    cudaFuncSetAttribute(lstm_kernel, cudaFuncAttributeMaxDynamicSharedMemorySize,
                         SMEM_BYTES);
    const float* x     = (const float*)d_in[0];
    const float* hprev = (const float*)d_in[1];
    const float* cprev = (const float*)d_in[2];
    const float* wxi   = (const float*)d_in[3];
    const float* wxf   = (const float*)d_in[4];
    const float* wxg   = (const float*)d_in[5];
    const float* wxo   = (const float*)d_in[6];
    const float* whi   = (const float*)d_in[7];
    const float* whf   = (const float*)d_in[8];
    const float* whg   = (const float*)d_in[9];
    const float* who   = (const float*)d_in[10];
    const float* bi    = (const float*)d_in[11];
    const float* bf    = (const float*)d_in[12];
    const float* bg    = (const float*)d_in[13];
    const float* bo    = (const float*)d_in[14];

    float* outh = (float*)d_out;
    const long long need2 = 2LL * BH;
    int writeC = ((long long)out_size >= need2) ? 1 : 0;
    float* outc = outh + BH;

    pack_weights<<<256, 256>>>(wxi, wxf, wxg, wxo, whi, whf, whg, who);
    lstm_kernel<<<GRID, THREADS, SMEM_BYTES>>>(
        x, hprev, cprev, bi, bf, bg, bo, outh, outc, writeC);
}

// round 11
// speedup vs baseline: 2.0495x; 1.0821x over previous
#include <cuda_runtime.h>
#include <cuda_fp16.h>
#include <cstdint>

#define DEVINL __device__ __forceinline__

namespace {

constexpr int HDIM = 128;
constexpr long long BROWS = 131072;
constexpr long long BH = BROWS * (long long)HDIM;
constexpr int THREADS = 512;
constexpr int M_TILE = 64;
constexpr int GRID = (int)(BROWS / M_TILE);  // 2048

// smem word (uint32) offsets
constexpr int SW_BIAS = 0;                      // 512 words fp32
constexpr int SW_A = 512;                       // packed A frags: 4bm*16ks*33 uint4
constexpr int A_WORDS = 4 * 16 * 33 * 4;        // 8448
constexpr int SW_RAW = SW_A + A_WORDS;          // 8960; 4 slots x 1024 words fp32
constexpr int RAW_SLOT = 1024;
constexpr int SW_B = SW_RAW + 4 * RAW_SLOT;     // 13056; 6 slots x 4096 words
constexpr int B_SLOT = 4096;
constexpr int SMEM_WORDS = SW_B + 6 * B_SLOT;   // 37632
constexpr int SMEM_BYTES = SMEM_WORDS * 4;      // 150528 -> 1 CTA/SM

// Pre-packed weights, fragment order:
// word idx = ks*4096 + fq*128 + lane*4 + wq;  fq = g*8 + wN; wq = subn*2 + bsel
__device__ uint32_t g_wpack[16 * 32 * 128];     // 65536 words, 256 KB

DEVINL void cp16(uint32_t saddr, const void* gaddr) {
    asm volatile("cp.async.cg.shared.global [%0], [%1], 16;"
                 :: "r"(saddr), "l"(gaddr) : "memory");
}
DEVINL void cp_commit() { asm volatile("cp.async.commit_group;" ::: "memory"); }

DEVINL uint32_t packh2(float lo, float hi) {
    __half2 h = __floats2half2_rn(lo, hi);
    return *reinterpret_cast<uint32_t*>(&h);
}

DEVINL void mma16(float* d, const uint4& a, uint32_t b0, uint32_t b1) {
    asm volatile(
        "mma.sync.aligned.m16n8k16.row.col.f32.f16.f16.f32 "
        "{%0,%1,%2,%3}, {%4,%5,%6,%7}, {%8,%9}, {%0,%1,%2,%3};"
        : "+f"(d[0]), "+f"(d[1]), "+f"(d[2]), "+f"(d[3])
        : "r"(a.x), "r"(a.y), "r"(a.z), "r"(a.w), "r"(b0), "r"(b1));
}

DEVINL float sigf(float x) {
    return __fdividef(1.0f, 1.0f + __expf(-x));
}
DEVINL float tanhfast(float x) {
    return __fdividef(2.0f, 1.0f + __expf(-2.0f * x)) - 1.0f;
}

// Packed A word index for fp16x2 word holding (r,k),(r,k+1), k even; r 0..63.
// Consumer reads uint4 at ((bm*16 + ks)*33 + lane), bm = r>>4 in 0..3.
DEVINL int widx(int r, int k) {
    int bm = r >> 4, rb = r & 15, ks = k >> 4, kr = k & 15;
    int lane_f = ((rb & 7) << 2) | ((kr & 7) >> 1);
    int q = ((kr >> 3) << 1) | (rb >> 3);
    return (((bm * 16 + ks) * 33 + lane_f) << 2) + q;
}

// ---- pre-pack: weights fp32 -> fp16x2 fragment-ordered image (256 KB) ----
__global__ void pack_weights(const float* __restrict__ wxi, const float* __restrict__ wxf,
                             const float* __restrict__ wxg, const float* __restrict__ wxo,
                             const float* __restrict__ whi, const float* __restrict__ whf,
                             const float* __restrict__ whg, const float* __restrict__ who) {
    const float* wx[4] = {wxi, wxf, wxg, wxo};
    const float* wh[4] = {whi, whf, whg, who};
    int idx = blockIdx.x * blockDim.x + threadIdx.x;  // 0..65535
    int wq = idx & 3;
    int lane = (idx >> 2) & 31;
    int fq = (idx >> 7) & 31;
    int ks = (idx >> 12) & 15;
    int g = fq >> 3, wN = fq & 7;
    int subn = wq >> 1, bsel = wq & 1;
    int n = wN * 16 + subn * 8 + (lane >> 2);
    int k0 = ks * 16 + 2 * (lane & 3) + bsel * 8;
    const float* w = (k0 < 128) ? wx[g] : wh[g];
    int kk = k0 & 127;
    float lo = w[(size_t)kk * HDIM + n];
    float hi = w[(size_t)(kk + 1) * HDIM + n];
    g_wpack[idx] = packh2(lo, hi);
}

// Issue cp.async group for k-step ks: B[ks] (16 KB) + raw A[ks] (4 KB fp32).
DEVINL void issue_group(int ks, uint32_t smem_u32, int tid,
                        const float* __restrict__ x, const float* __restrict__ h,
                        long long row0) {
    const uint32_t bdst = smem_u32 + (uint32_t)((SW_B + (ks % 6) * B_SLOT) * 4);
    const uint32_t* src = g_wpack + ks * 4096;
    cp16(bdst + tid * 16, src + tid * 4);
    cp16(bdst + (tid + 512) * 16, src + (tid + 512) * 4);
    if (tid < 256) {
        int r = tid >> 2, c4 = tid & 3;
        const float* gsrc = ((ks < 8) ? x : h) + (row0 + r) * HDIM + (ks & 7) * 16 + c4 * 4;
        cp16(smem_u32 + (uint32_t)((SW_RAW + (ks % 4) * RAW_SLOT) * 4) + tid * 16, gsrc);
    }
    cp_commit();
}

__global__ void __launch_bounds__(THREADS, 1)
lstm_kernel(const float* __restrict__ x, const float* __restrict__ hprev,
            const float* __restrict__ cprev,
            const float* __restrict__ bi, const float* __restrict__ bf,
            const float* __restrict__ bg, const float* __restrict__ bo,
            float* __restrict__ outh, float* __restrict__ outc, int writeC) {
    extern __shared__ float sm[];
    uint32_t* smw = reinterpret_cast<uint32_t*>(sm);
    const int tid = threadIdx.x;
    const int lane = tid & 31;
    const int wid = tid >> 5;
    const int wM = wid >> 3;  // 0..1 (32 rows each)
    const int wN = wid & 7;   // 0..7 (16 h-cols each)
    const long long row0 = (long long)blockIdx.x * M_TILE;
    const uint32_t smem_u32 = (uint32_t)__cvta_generic_to_shared(sm);

    // Prologue: 4-deep pipeline of (B[ks] + rawA[ks]) groups.
    issue_group(0, smem_u32, tid, x, hprev, row0);
    issue_group(1, smem_u32, tid, x, hprev, row0);
    issue_group(2, smem_u32, tid, x, hprev, row0);
    issue_group(3, smem_u32, tid, x, hprev, row0);

    // biases [i|f|g|o] x 128
    {
        int g = tid >> 7, e = tid & 127;
        const float* bsrc = (g == 0) ? bi : (g == 1) ? bf : (g == 2) ? bg : bo;
        sm[SW_BIAS + tid] = bsrc[e];
    }

    float acc[2][8][4];
#pragma unroll
    for (int mi = 0; mi < 2; mi++)
#pragma unroll
        for (int f = 0; f < 8; f++)
#pragma unroll
            for (int q = 0; q < 4; q++) acc[mi][f][q] = 0.0f;

    const uint4* apack = reinterpret_cast<const uint4*>(smw + SW_A);

#define STEP(ks, W)                                                            \
    {                                                                          \
        asm volatile("cp.async.wait_group %0;" :: "n"(W) : "memory");          \
        __syncthreads();                                                       \
        /* convert raw fp32 chunk ks -> packed fp16 A frags */                 \
        {                                                                      \
            const float* raw = sm + SW_RAW + ((ks) % 4) * RAW_SLOT;            \
            float2 f2 = *reinterpret_cast<const float2*>(raw + tid * 2);       \
            int rr = tid >> 3, kw = tid & 7;                                   \
            smw[SW_A + widx(rr, (ks) * 16 + kw * 2)] = packh2(f2.x, f2.y);     \
        }                                                                      \
        __syncthreads();                                                       \
        if ((ks) + 4 < 16) issue_group((ks) + 4, smem_u32, tid, x, hprev, row0);\
        /* compute k-step ks */                                                \
        {                                                                      \
            uint4 a0 = apack[((wM * 2 + 0) * 16 + (ks)) * 33 + lane];          \
            uint4 a1 = apack[((wM * 2 + 1) * 16 + (ks)) * 33 + lane];          \
            const uint4* bp = reinterpret_cast<const uint4*>(                  \
                smw + SW_B + ((ks) % 6) * B_SLOT);                             \
            _Pragma("unroll")                                                  \
            for (int g = 0; g < 4; g++) {                                      \
                uint4 bv = bp[(g * 8 + wN) * 32 + lane];                       \
                mma16(acc[0][g * 2 + 0], a0, bv.x, bv.y);                      \
                mma16(acc[0][g * 2 + 1], a0, bv.z, bv.w);                      \
                mma16(acc[1][g * 2 + 0], a1, bv.x, bv.y);                      \
                mma16(acc[1][g * 2 + 1], a1, bv.z, bv.w);                      \
            }                                                                  \
        }                                                                      \
    }

    STEP(0, 3)  STEP(1, 3)  STEP(2, 3)  STEP(3, 3)
    STEP(4, 3)  STEP(5, 3)  STEP(6, 3)  STEP(7, 3)
    STEP(8, 3)  STEP(9, 3)  STEP(10, 3) STEP(11, 3)
    STEP(12, 3) STEP(13, 2) STEP(14, 1) STEP(15, 0)
#undef STEP

    // Epilogue: warp owns h-cols [wN*16, wN*16+16), rows wM*32..+32; all gates.
    const float* bsm = sm + SW_BIAS;
#pragma unroll
    for (int mi = 0; mi < 2; mi++) {
#pragma unroll
        for (int rh = 0; rh < 2; rh++) {
            const long long m = row0 + wM * 32 + mi * 16 + (lane >> 2) + rh * 8;
#pragma unroll
            for (int subn = 0; subn < 2; subn++) {
                const int n = wN * 16 + subn * 8 + 2 * (lane & 3);
                float2 cp2 = *reinterpret_cast<const float2*>(cprev + m * HDIM + n);
                float hv[2], cv[2];
#pragma unroll
                for (int col = 0; col < 2; col++) {
                    float ai = acc[mi][0 * 2 + subn][rh * 2 + col] + bsm[n + col];
                    float af = acc[mi][1 * 2 + subn][rh * 2 + col] + bsm[128 + n + col];
                    float ag = acc[mi][2 * 2 + subn][rh * 2 + col] + bsm[256 + n + col];
                    float ao = acc[mi][3 * 2 + subn][rh * 2 + col] + bsm[384 + n + col];
                    float ig = sigf(ai);
                    float fg = sigf(af);
                    float og = sigf(ao);
                    float gg = tanhfast(ag);
                    float cpv = (col == 0) ? cp2.x : cp2.y;
                    float ct = fg * cpv + ig * gg;
                    cv[col] = ct;
                    hv[col] = og * tanhfast(ct);
                }
                *reinterpret_cast<float2*>(outh + m * HDIM + n) =
                    make_float2(hv[0], hv[1]);
                if (writeC) {
                    *reinterpret_cast<float2*>(outc + m * HDIM + n) =
                        make_float2(cv[0], cv[1]);
                }
            }
        }
    }
}

}  // namespace

extern "C" void kernel_launch(void* const* d_in, const int* in_sizes, int n_in,
                              void* d_out, int out_size) {
    (void)in_sizes; (void)n_in;
    cudaFuncSetAttribute(lstm_kernel, cudaFuncAttributeMaxDynamicSharedMemorySize,
                         SMEM_BYTES);
    const float* x     = (const float*)d_in[0];
    const float* hprev = (const float*)d_in[1];
    const float* cprev = (const float*)d_in[2];
    const float* wxi   = (const float*)d_in[3];
    const float* wxf   = (const float*)d_in[4];
    const float* wxg   = (const float*)d_in[5];
    const float* wxo   = (const float*)d_in[6];
    const float* whi   = (const float*)d_in[7];
    const float* whf   = (const float*)d_in[8];
    const float* whg   = (const float*)d_in[9];
    const float* who   = (const float*)d_in[10];
    const float* bi    = (const float*)d_in[11];
    const float* bf    = (const float*)d_in[12];
    const float* bg    = (const float*)d_in[13];
    const float* bo    = (const float*)d_in[14];

    float* outh = (float*)d_out;
    const long long need2 = 2LL * BH;
    int writeC = ((long long)out_size >= need2) ? 1 : 0;
    float* outc = outh + BH;

    pack_weights<<<256, 256>>>(wxi, wxf, wxg, wxo, whi, whf, whg, who);
    lstm_kernel<<<GRID, THREADS, SMEM_BYTES>>>(
        x, hprev, cprev, bi, bf, bg, bo, outh, outc, writeC);
}